// round 2
// baseline (speedup 1.0000x reference)
#include <cuda_runtime.h>
#include <math.h>

#define N_NODES 100000
#define N_EDGES 1600000
#define N_GRAPHS 256
#define C_IN 128
#define DD 64
#define EPS 1e-5f
#define SLOPE 0.01f

// ---------------- scratch (device globals; no cudaMalloc allowed) ----------
__device__ float  g_deg[N_NODES];
__device__ float  g_dinv[N_NODES];
__device__ float  g_dinv2[N_NODES];
__device__ int    g_cnt[N_NODES];
__device__ int    g_rowptr[N_NODES + 1];
__device__ int    g_fill[N_NODES];
__device__ int    g_bsum[128];
__device__ int    g_boff[128];
__device__ int    g_csrc[N_EDGES];
__device__ float  g_cnorm[N_EDGES];
__device__ float  g_t[N_NODES * DD];   // gemm output
__device__ float  g_h[N_NODES * DD];   // activations
__device__ double g_sum[DD];
__device__ double g_sumsq[DD];
__device__ float  g_mean[DD];
__device__ float  g_rstd[DD];
__device__ float  g_pooled[N_GRAPHS * 2 * DD];

// ---------------- init / degree ----------------
__global__ void zero_kernel() {
    int i = blockIdx.x * blockDim.x + threadIdx.x;
    if (i < N_NODES) { g_deg[i] = 0.f; g_cnt[i] = 0; g_fill[i] = 0; }
}

__global__ void degcnt_kernel(const int* __restrict__ src, const int* __restrict__ dst,
                              const float* __restrict__ w) {
    int e = blockIdx.x * blockDim.x + threadIdx.x;
    if (e < N_EDGES) {
        int d = dst[e];
        atomicAdd(&g_deg[d], w[e]);
        atomicAdd(&g_cnt[d], 1);
    }
}

__global__ void dinv_kernel() {
    int i = blockIdx.x * blockDim.x + threadIdx.x;
    if (i < N_NODES) {
        float dg = g_deg[i] + 1.0f;           // self loop weight 1
        float di = rsqrtf(dg);
        g_dinv[i]  = di;
        g_dinv2[i] = di * di;
    }
}

// ---------------- 3-phase exclusive scan of g_cnt -> g_rowptr ----------------
__global__ void scan1_kernel() {
    __shared__ int s[1024];
    int tid = threadIdx.x;
    int i = blockIdx.x * 1024 + tid;
    int v = (i < N_NODES) ? g_cnt[i] : 0;
    s[tid] = v;
    __syncthreads();
    for (int off = 1; off < 1024; off <<= 1) {
        int t = (tid >= off) ? s[tid - off] : 0;
        __syncthreads();
        s[tid] += t;
        __syncthreads();
    }
    if (i < N_NODES) g_rowptr[i] = s[tid] - v;      // exclusive within block
    if (tid == 1023) g_bsum[blockIdx.x] = s[1023];  // block total
}

__global__ void scan2_kernel(int nb) {
    __shared__ int s[128];
    int tid = threadIdx.x;
    int v = (tid < nb) ? g_bsum[tid] : 0;
    s[tid] = v;
    __syncthreads();
    for (int off = 1; off < 128; off <<= 1) {
        int t = (tid >= off) ? s[tid - off] : 0;
        __syncthreads();
        s[tid] += t;
        __syncthreads();
    }
    if (tid < nb) g_boff[tid] = s[tid] - v;
}

__global__ void scan3_kernel() {
    int i = blockIdx.x * blockDim.x + threadIdx.x;
    if (i < N_NODES) g_rowptr[i] += g_boff[i >> 10];
    if (i == 0) g_rowptr[N_NODES] = N_EDGES;
}

// ---------------- CSR fill ----------------
__global__ void csrfill_kernel(const int* __restrict__ src, const int* __restrict__ dst,
                               const float* __restrict__ w) {
    int e = blockIdx.x * blockDim.x + threadIdx.x;
    if (e < N_EDGES) {
        int d = dst[e], s = src[e];
        int pos = g_rowptr[d] + atomicAdd(&g_fill[d], 1);
        g_csrc[pos]  = s;
        g_cnorm[pos] = g_dinv[s] * w[e] * g_dinv[d];
    }
}

// ---------------- GEMM: X[N,C] @ W[C,64] -> g_t[N,64] ----------------
// FROM_GH=true reads the device-global g_h (symbol resolved *inside* the
// kernel); FROM_GH=false reads the Xparam pointer (harness d_in memory).
template<int C, int RPB, bool FROM_GH>
__global__ __launch_bounds__(256)
void gemm_kernel(const float* __restrict__ Xparam, const float* __restrict__ W) {
    __shared__ float Ws[C * 64];
    __shared__ float Xs[RPB * C];
    constexpr int RPT = RPB / 16;
    const float* __restrict__ X = FROM_GH ? (const float*)g_h : Xparam;
    int tid = threadIdx.x;
    int rowBase = blockIdx.x * RPB;

    for (int idx = tid; idx < C * 64; idx += 256) Ws[idx] = W[idx];
    for (int idx = tid; idx < RPB * C; idx += 256) {
        int r = idx / C, c = idx % C;
        int gr = rowBase + r;
        Xs[idx] = (gr < N_NODES) ? X[(size_t)gr * C + c] : 0.f;
    }
    __syncthreads();

    int tx = tid & 15, ty = tid >> 4;
    float acc[RPT][4];
#pragma unroll
    for (int r = 0; r < RPT; r++)
#pragma unroll
        for (int j = 0; j < 4; j++) acc[r][j] = 0.f;

    const float* xp = Xs + (ty * RPT) * C;
#pragma unroll 4
    for (int k = 0; k < C; k++) {
        float4 b = *(const float4*)(Ws + k * 64 + tx * 4);
#pragma unroll
        for (int r = 0; r < RPT; r++) {
            float a = xp[r * C + k];
            acc[r][0] += a * b.x;
            acc[r][1] += a * b.y;
            acc[r][2] += a * b.z;
            acc[r][3] += a * b.w;
        }
    }

#pragma unroll
    for (int r = 0; r < RPT; r++) {
        int gr = rowBase + ty * RPT + r;
        if (gr < N_NODES) {
            float4 v;
            v.x = acc[r][0]; v.y = acc[r][1]; v.z = acc[r][2]; v.w = acc[r][3];
            *(float4*)(&g_t[gr * 64 + tx * 4]) = v;
        }
    }
}

// ---------------- aggregation: g_h = A @ g_t + bias (warp per node) --------
__global__ void agg_kernel(const float* __restrict__ bias, int do_lrelu) {
    int w = (blockIdx.x * blockDim.x + threadIdx.x) >> 5;
    int lane = threadIdx.x & 31;
    if (w >= N_NODES) return;

    float d2 = g_dinv2[w];
    float2 t0 = *(const float2*)(g_t + (size_t)w * 64 + lane * 2);
    float ax = t0.x * d2, ay = t0.y * d2;

    int beg = g_rowptr[w], end = g_rowptr[w + 1];
    for (int e = beg; e < end; e++) {
        int s = g_csrc[e];
        float nn = g_cnorm[e];
        float2 v = *(const float2*)(g_t + (size_t)s * 64 + lane * 2);
        ax += v.x * nn;
        ay += v.y * nn;
    }
    ax += bias[lane * 2];
    ay += bias[lane * 2 + 1];
    if (do_lrelu) {
        ax = ax > 0.f ? ax : SLOPE * ax;
        ay = ay > 0.f ? ay : SLOPE * ay;
    }
    float2 o; o.x = ax; o.y = ay;
    *(float2*)(g_h + (size_t)w * 64 + lane * 2) = o;
}

// ---------------- batch norm ----------------
__global__ void bn_zero_kernel() {
    int c = threadIdx.x;
    if (c < DD) { g_sum[c] = 0.0; g_sumsq[c] = 0.0; }
}

__global__ void bnstats_kernel() {
    int c = threadIdx.x & 63;
    int r0 = (blockIdx.x * blockDim.x + threadIdx.x) >> 6;
    int stride = (gridDim.x * blockDim.x) >> 6;
    double s = 0.0, s2 = 0.0;
    for (int r = r0; r < N_NODES; r += stride) {
        float v = g_h[(size_t)r * 64 + c];
        s += (double)v;
        s2 += (double)v * (double)v;
    }
    atomicAdd(&g_sum[c], s);
    atomicAdd(&g_sumsq[c], s2);
}

__global__ void bnfinal_kernel() {
    int c = threadIdx.x;
    if (c < DD) {
        double m = g_sum[c] / (double)N_NODES;
        double var = g_sumsq[c] / (double)N_NODES - m * m;
        g_mean[c] = (float)m;
        g_rstd[c] = rsqrtf((float)var + EPS);
    }
}

__global__ void bnapply_kernel(const float* __restrict__ gamma, const float* __restrict__ beta) {
    int idx = blockIdx.x * blockDim.x + threadIdx.x;
    if (idx < N_NODES * 64) {
        int c = idx & 63;
        float v = (g_h[idx] - g_mean[c]) * g_rstd[c] * gamma[c] + beta[c];
        g_h[idx] = v > 0.f ? v : SLOPE * v;
    }
}

// ---------------- pooling (block per graph, batch is sorted) ----------------
__device__ __forceinline__ int lower_bound_dev(const int* a, int n, int key) {
    int lo = 0, hi = n;
    while (lo < hi) {
        int mid = (lo + hi) >> 1;
        if (a[mid] < key) lo = mid + 1; else hi = mid;
    }
    return lo;
}

__global__ void pool_kernel(const int* __restrict__ batch) {
    __shared__ int s_beg, s_end;
    __shared__ float smx[256], ssm[256];
    int g = blockIdx.x;
    if (threadIdx.x == 0) s_beg = lower_bound_dev(batch, N_NODES, g);
    if (threadIdx.x == 1) s_end = lower_bound_dev(batch, N_NODES, g + 1);
    __syncthreads();
    int beg = s_beg, end = s_end;

    int c = threadIdx.x & 63, grp = threadIdx.x >> 6;
    float mx = -3.402823466e38f;
    float sm = 0.f;
    for (int i = beg + grp; i < end; i += 4) {
        float v = g_h[(size_t)i * 64 + c];
        mx = fmaxf(mx, v);
        sm += v;
    }
    smx[threadIdx.x] = mx;
    ssm[threadIdx.x] = sm;
    __syncthreads();
    if (grp == 0) {
        for (int j = 1; j < 4; j++) {
            mx = fmaxf(mx, smx[j * 64 + c]);
            sm += ssm[j * 64 + c];
        }
        int cnt = end - beg;
        float denom = (float)(cnt > 1 ? cnt : 1);
        g_pooled[g * 128 + c]      = mx;
        g_pooled[g * 128 + 64 + c] = sm / denom;
    }
}

// ---------------- FC: pooled[G,128] @ Wfc[128,1] + bfc ----------------
__global__ void fc_kernel(const float* __restrict__ Wfc, const float* __restrict__ bfc,
                          float* __restrict__ out) {
    int g = (blockIdx.x * blockDim.x + threadIdx.x) >> 5;
    int lane = threadIdx.x & 31;
    if (g >= N_GRAPHS) return;
    float s = 0.f;
    for (int i = lane; i < 128; i += 32) s += g_pooled[g * 128 + i] * Wfc[i];
#pragma unroll
    for (int o = 16; o; o >>= 1) s += __shfl_down_sync(0xFFFFFFFFu, s, o);
    if (lane == 0) out[g] = s + bfc[0];
}

// ---------------- launch ----------------
extern "C" void kernel_launch(void* const* d_in, const int* in_sizes, int n_in,
                              void* d_out, int out_size) {
    const float* x     = (const float*)d_in[0];
    const int*   ei    = (const int*)  d_in[1];
    const int*   batch = (const int*)  d_in[2];
    const float* ea    = (const float*)d_in[3];
    const float* W0 = (const float*)d_in[4];
    const float* b0 = (const float*)d_in[5];
    const float* g0 = (const float*)d_in[6];
    const float* be0 = (const float*)d_in[7];
    const float* W1 = (const float*)d_in[8];
    const float* b1 = (const float*)d_in[9];
    const float* g1 = (const float*)d_in[10];
    const float* be1 = (const float*)d_in[11];
    const float* W2 = (const float*)d_in[12];
    const float* b2 = (const float*)d_in[13];
    const float* W3 = (const float*)d_in[14];
    const float* b3 = (const float*)d_in[15];
    const float* Wfc = (const float*)d_in[16];
    const float* bfc = (const float*)d_in[17];
    float* out = (float*)d_out;

    const int* src = ei;
    const int* dst = ei + N_EDGES;

    const int TB = 256;
    int nB_nodes = (N_NODES + TB - 1) / TB;
    int nB_edges = (N_EDGES + TB - 1) / TB;
    int nScan1 = (N_NODES + 1023) / 1024;       // 98
    int nB_agg = (N_NODES * 32 + TB - 1) / TB;  // warp per node

    // --- structure build (once per replay) ---
    zero_kernel<<<nB_nodes, TB>>>();
    degcnt_kernel<<<nB_edges, TB>>>(src, dst, ea);
    dinv_kernel<<<nB_nodes, TB>>>();
    scan1_kernel<<<nScan1, 1024>>>();
    scan2_kernel<<<1, 128>>>(nScan1);
    scan3_kernel<<<nB_nodes, TB>>>();
    csrfill_kernel<<<nB_edges, TB>>>(src, dst, ea);

    // --- layer 0: gemm(C=128, reads d_in x) -> agg -> BN -> lrelu ---
    gemm_kernel<128, 32, false><<<(N_NODES + 31) / 32, 256>>>(x, W0);
    agg_kernel<<<nB_agg, TB>>>(b0, 0);
    bn_zero_kernel<<<1, 64>>>();
    bnstats_kernel<<<512, 256>>>();
    bnfinal_kernel<<<1, 64>>>();
    bnapply_kernel<<<(N_NODES * 64 + TB - 1) / TB, TB>>>(g0, be0);

    // --- layer 1: gemm(C=64, reads g_h) -> agg -> BN -> lrelu ---
    gemm_kernel<64, 64, true><<<(N_NODES + 63) / 64, 256>>>(nullptr, W1);
    agg_kernel<<<nB_agg, TB>>>(b1, 0);
    bn_zero_kernel<<<1, 64>>>();
    bnstats_kernel<<<512, 256>>>();
    bnfinal_kernel<<<1, 64>>>();
    bnapply_kernel<<<(N_NODES * 64 + TB - 1) / TB, TB>>>(g1, be1);

    // --- layer 2: gemm -> agg(+lrelu) ---
    gemm_kernel<64, 64, true><<<(N_NODES + 63) / 64, 256>>>(nullptr, W2);
    agg_kernel<<<nB_agg, TB>>>(b2, 1);

    // --- layer 3: gemm -> agg(+lrelu) ---
    gemm_kernel<64, 64, true><<<(N_NODES + 63) / 64, 256>>>(nullptr, W3);
    agg_kernel<<<nB_agg, TB>>>(b3, 1);

    // --- pooling + FC ---
    pool_kernel<<<N_GRAPHS, 256>>>(batch);
    fc_kernel<<<(N_GRAPHS * 32 + TB - 1) / TB, TB>>>(Wfc, bfc, out);
}

// round 3
// speedup vs baseline: 1.1613x; 1.1613x over previous
#include <cuda_runtime.h>
#include <math.h>

#define N_NODES 100000
#define N_EDGES 1600000
#define N_GRAPHS 256
#define C_IN 128
#define DD 64
#define EPS 1e-5f
#define SLOPE 0.01f

// ---------------- scratch (device globals; no cudaMalloc allowed) ----------
__device__ float  g_dinv[N_NODES];
__device__ float  g_dinv2[N_NODES];
__device__ float  g_deg[N_NODES];
__device__ int    g_cnt[N_NODES];
__device__ int    g_rowptr[N_NODES + 1];
__device__ int    g_fill[N_NODES];
__device__ int    g_bsum[128];
__device__ int    g_boff[128];
__device__ int2   g_epack[N_EDGES];          // {src, norm-as-int}
__device__ float  g_t[N_NODES * DD];         // gemm output
__device__ float  g_h[N_NODES * DD];         // activations
__device__ double g_sum[2][DD];
__device__ double g_sumsq[2][DD];
__device__ float  g_mean[2][DD];
__device__ float  g_rstd[2][DD];
__device__ float  g_pooled[N_GRAPHS * 2 * DD];

// ---------------- f32x2 packed math helpers ----------------
__device__ __forceinline__ unsigned long long pk2(float lo, float hi) {
    unsigned long long r;
    asm("mov.b64 %0, {%1, %2};" : "=l"(r) : "f"(lo), "f"(hi));
    return r;
}
__device__ __forceinline__ void fma2(unsigned long long& d, unsigned long long a,
                                     unsigned long long b) {
    asm("fma.rn.f32x2 %0, %1, %2, %3;" : "=l"(d) : "l"(a), "l"(b), "l"(d));
}
__device__ __forceinline__ void upk2(float& lo, float& hi, unsigned long long v) {
    asm("mov.b64 {%0, %1}, %2;" : "=f"(lo), "=f"(hi) : "l"(v));
}

// ---------------- init / degree ----------------
__global__ void zero_kernel() {
    int i = blockIdx.x * blockDim.x + threadIdx.x;
    if (i < N_NODES) { g_deg[i] = 0.f; g_cnt[i] = 0; g_fill[i] = 0; }
    if (i < 128) {
        g_sum[i >> 6][i & 63] = 0.0;
        g_sumsq[i >> 6][i & 63] = 0.0;
    }
}

__global__ void degcnt_kernel(const int* __restrict__ src, const int* __restrict__ dst,
                              const float* __restrict__ w) {
    int e = blockIdx.x * blockDim.x + threadIdx.x;
    if (e < N_EDGES) {
        int d = dst[e];
        atomicAdd(&g_deg[d], w[e]);
        atomicAdd(&g_cnt[d], 1);
    }
}

__global__ void dinv_kernel() {
    int i = blockIdx.x * blockDim.x + threadIdx.x;
    if (i < N_NODES) {
        float dg = g_deg[i] + 1.0f;           // self loop weight 1
        float di = rsqrtf(dg);
        g_dinv[i]  = di;
        g_dinv2[i] = di * di;
    }
}

// ---------------- 3-phase exclusive scan of g_cnt -> g_rowptr ----------------
__global__ void scan1_kernel() {
    __shared__ int s[1024];
    int tid = threadIdx.x;
    int i = blockIdx.x * 1024 + tid;
    int v = (i < N_NODES) ? g_cnt[i] : 0;
    s[tid] = v;
    __syncthreads();
    for (int off = 1; off < 1024; off <<= 1) {
        int t = (tid >= off) ? s[tid - off] : 0;
        __syncthreads();
        s[tid] += t;
        __syncthreads();
    }
    if (i < N_NODES) g_rowptr[i] = s[tid] - v;
    if (tid == 1023) g_bsum[blockIdx.x] = s[1023];
}

__global__ void scan2_kernel(int nb) {
    __shared__ int s[128];
    int tid = threadIdx.x;
    int v = (tid < nb) ? g_bsum[tid] : 0;
    s[tid] = v;
    __syncthreads();
    for (int off = 1; off < 128; off <<= 1) {
        int t = (tid >= off) ? s[tid - off] : 0;
        __syncthreads();
        s[tid] += t;
        __syncthreads();
    }
    if (tid < nb) g_boff[tid] = s[tid] - v;
}

__global__ void scan3_kernel() {
    int i = blockIdx.x * blockDim.x + threadIdx.x;
    if (i < N_NODES) g_rowptr[i] += g_boff[i >> 10];
    if (i == 0) g_rowptr[N_NODES] = N_EDGES;
}

// ---------------- CSR fill (packed 8B records) ----------------
__global__ void csrfill_kernel(const int* __restrict__ src, const int* __restrict__ dst,
                               const float* __restrict__ w) {
    int e = blockIdx.x * blockDim.x + threadIdx.x;
    if (e < N_EDGES) {
        int d = dst[e], s = src[e];
        int pos = g_rowptr[d] + atomicAdd(&g_fill[d], 1);
        int2 pr;
        pr.x = s;
        pr.y = __float_as_int(g_dinv[s] * w[e] * g_dinv[d]);
        g_epack[pos] = pr;
    }
}

// ---------------- GEMM: X[N,C] @ W[C,64] -> g_t[N,64] with f32x2 FMAs ------
// Xs stored column-major with pad RPB+2 so row-pairs load as 8B vectors.
// BNFUSE applies (v - mean)*rstd*gamma + beta then LeakyReLU on load.
template<int C, bool FROM_GH, bool BNFUSE>
__global__ __launch_bounds__(256)
void gemm_kernel(const float* __restrict__ Xparam, const float* __restrict__ W,
                 const float* __restrict__ gamma, const float* __restrict__ beta,
                 int bnlayer) {
    constexpr int RPB = 64;
    constexpr int RPBp = RPB + 2;   // 8B-aligned padded column stride
    constexpr int RPT = 4;
    extern __shared__ float smem[];
    float* Ws = smem;               // [C][64]
    float* Xs = smem + C * 64;      // [C][RPBp], column-major tile

    const float* __restrict__ X = FROM_GH ? (const float*)g_h : Xparam;
    int tid = threadIdx.x;
    int rowBase = blockIdx.x * RPB;

    for (int idx = tid; idx < C * 64; idx += 256) Ws[idx] = W[idx];
    for (int idx = tid; idx < RPB * C; idx += 256) {
        int r = idx / C, c = idx % C;
        int gr = rowBase + r;
        float v = (gr < N_NODES) ? X[(size_t)gr * C + c] : 0.f;
        if (BNFUSE) {
            v = (v - g_mean[bnlayer][c]) * g_rstd[bnlayer][c] * gamma[c] + beta[c];
            v = v > 0.f ? v : SLOPE * v;
        }
        Xs[c * RPBp + r] = v;
    }
    __syncthreads();

    int tx = tid & 15, ty = tid >> 4;
    int rbase = ty * RPT;

    unsigned long long acc[RPT / 2][4];
#pragma unroll
    for (int p = 0; p < RPT / 2; p++)
#pragma unroll
        for (int j = 0; j < 4; j++) acc[p][j] = 0ull;

#pragma unroll 8
    for (int k = 0; k < C; k++) {
        float4 b = *(const float4*)(Ws + k * 64 + tx * 4);
        unsigned long long b0 = pk2(b.x, b.x);
        unsigned long long b1 = pk2(b.y, b.y);
        unsigned long long b2 = pk2(b.z, b.z);
        unsigned long long b3 = pk2(b.w, b.w);
        const float* col = Xs + k * RPBp + rbase;
#pragma unroll
        for (int p = 0; p < RPT / 2; p++) {
            unsigned long long a = *(const unsigned long long*)(col + p * 2);
            fma2(acc[p][0], a, b0);
            fma2(acc[p][1], a, b1);
            fma2(acc[p][2], a, b2);
            fma2(acc[p][3], a, b3);
        }
    }

#pragma unroll
    for (int p = 0; p < RPT / 2; p++) {
        float lo0, hi0, lo1, hi1, lo2, hi2, lo3, hi3;
        upk2(lo0, hi0, acc[p][0]);
        upk2(lo1, hi1, acc[p][1]);
        upk2(lo2, hi2, acc[p][2]);
        upk2(lo3, hi3, acc[p][3]);
        int gr0 = rowBase + rbase + p * 2;
        if (gr0 < N_NODES) {
            float4 v; v.x = lo0; v.y = lo1; v.z = lo2; v.w = lo3;
            *(float4*)(&g_t[(size_t)gr0 * 64 + tx * 4]) = v;
        }
        if (gr0 + 1 < N_NODES) {
            float4 v; v.x = hi0; v.y = hi1; v.z = hi2; v.w = hi3;
            *(float4*)(&g_t[(size_t)(gr0 + 1) * 64 + tx * 4]) = v;
        }
    }
}

// ---------------- aggregation: g_h = A @ g_t + bias (warp per node) --------
// 4-edge software pipeline: 4 independent row gathers in flight.
__global__ void agg_kernel(const float* __restrict__ bias, int do_lrelu) {
    int w = (blockIdx.x * blockDim.x + threadIdx.x) >> 5;
    int lane2 = (threadIdx.x & 31) * 2;
    if (w >= N_NODES) return;

    float d2 = g_dinv2[w];
    float2 t0 = *(const float2*)(g_t + (size_t)w * 64 + lane2);
    float ax = t0.x * d2, ay = t0.y * d2;

    int e = g_rowptr[w], end = g_rowptr[w + 1];
    for (; e + 4 <= end; e += 4) {
        int2 p0 = g_epack[e];
        int2 p1 = g_epack[e + 1];
        int2 p2 = g_epack[e + 2];
        int2 p3 = g_epack[e + 3];
        float2 v0 = *(const float2*)(g_t + (size_t)p0.x * 64 + lane2);
        float2 v1 = *(const float2*)(g_t + (size_t)p1.x * 64 + lane2);
        float2 v2 = *(const float2*)(g_t + (size_t)p2.x * 64 + lane2);
        float2 v3 = *(const float2*)(g_t + (size_t)p3.x * 64 + lane2);
        float n0 = __int_as_float(p0.y), n1 = __int_as_float(p1.y);
        float n2 = __int_as_float(p2.y), n3 = __int_as_float(p3.y);
        ax = fmaf(v0.x, n0, ax); ay = fmaf(v0.y, n0, ay);
        ax = fmaf(v1.x, n1, ax); ay = fmaf(v1.y, n1, ay);
        ax = fmaf(v2.x, n2, ax); ay = fmaf(v2.y, n2, ay);
        ax = fmaf(v3.x, n3, ax); ay = fmaf(v3.y, n3, ay);
    }
    for (; e < end; e++) {
        int2 p = g_epack[e];
        float2 v = *(const float2*)(g_t + (size_t)p.x * 64 + lane2);
        float nn = __int_as_float(p.y);
        ax = fmaf(v.x, nn, ax); ay = fmaf(v.y, nn, ay);
    }
    ax += bias[lane2];
    ay += bias[lane2 + 1];
    if (do_lrelu) {
        ax = ax > 0.f ? ax : SLOPE * ax;
        ay = ay > 0.f ? ay : SLOPE * ay;
    }
    float2 o; o.x = ax; o.y = ay;
    *(float2*)(g_h + (size_t)w * 64 + lane2) = o;
}

// ---------------- batch norm stats (block pre-reduced) ----------------
__global__ void bnstats_kernel(int layer) {
    __shared__ double ssum[256], ssq[256];
    int c = threadIdx.x & 63;
    int rlane = threadIdx.x >> 6;              // 0..3
    int r0 = blockIdx.x * 4 + rlane;
    int stride = gridDim.x * 4;
    double s = 0.0, s2 = 0.0;
    for (int r = r0; r < N_NODES; r += stride) {
        float v = g_h[(size_t)r * 64 + c];
        s += (double)v;
        s2 += (double)v * (double)v;
    }
    ssum[threadIdx.x] = s;
    ssq[threadIdx.x]  = s2;
    __syncthreads();
    if (rlane == 0) {
#pragma unroll
        for (int j = 1; j < 4; j++) {
            s  += ssum[j * 64 + c];
            s2 += ssq[j * 64 + c];
        }
        atomicAdd(&g_sum[layer][c], s);
        atomicAdd(&g_sumsq[layer][c], s2);
    }
}

__global__ void bnfinal_kernel(int layer) {
    int c = threadIdx.x;
    if (c < DD) {
        double m = g_sum[layer][c] / (double)N_NODES;
        double var = g_sumsq[layer][c] / (double)N_NODES - m * m;
        g_mean[layer][c] = (float)m;
        g_rstd[layer][c] = rsqrtf((float)var + EPS);
    }
}

// ---------------- pooling (block per graph, batch is sorted) ----------------
__device__ __forceinline__ int lower_bound_dev(const int* a, int n, int key) {
    int lo = 0, hi = n;
    while (lo < hi) {
        int mid = (lo + hi) >> 1;
        if (a[mid] < key) lo = mid + 1; else hi = mid;
    }
    return lo;
}

__global__ void pool_kernel(const int* __restrict__ batch) {
    __shared__ int s_beg, s_end;
    __shared__ float smx[256], ssm[256];
    int g = blockIdx.x;
    if (threadIdx.x == 0) s_beg = lower_bound_dev(batch, N_NODES, g);
    if (threadIdx.x == 1) s_end = lower_bound_dev(batch, N_NODES, g + 1);
    __syncthreads();
    int beg = s_beg, end = s_end;

    int c = threadIdx.x & 63, grp = threadIdx.x >> 6;
    float mx = -3.402823466e38f;
    float sm = 0.f;
    for (int i = beg + grp; i < end; i += 4) {
        float v = g_h[(size_t)i * 64 + c];
        mx = fmaxf(mx, v);
        sm += v;
    }
    smx[threadIdx.x] = mx;
    ssm[threadIdx.x] = sm;
    __syncthreads();
    if (grp == 0) {
        for (int j = 1; j < 4; j++) {
            mx = fmaxf(mx, smx[j * 64 + c]);
            sm += ssm[j * 64 + c];
        }
        int cnt = end - beg;
        float denom = (float)(cnt > 1 ? cnt : 1);
        g_pooled[g * 128 + c]      = mx;
        g_pooled[g * 128 + 64 + c] = sm / denom;
    }
}

// ---------------- FC: pooled[G,128] @ Wfc[128,1] + bfc ----------------
__global__ void fc_kernel(const float* __restrict__ Wfc, const float* __restrict__ bfc,
                          float* __restrict__ out) {
    int g = (blockIdx.x * blockDim.x + threadIdx.x) >> 5;
    int lane = threadIdx.x & 31;
    if (g >= N_GRAPHS) return;
    float s = 0.f;
    for (int i = lane; i < 128; i += 32) s += g_pooled[g * 128 + i] * Wfc[i];
#pragma unroll
    for (int o = 16; o; o >>= 1) s += __shfl_down_sync(0xFFFFFFFFu, s, o);
    if (lane == 0) out[g] = s + bfc[0];
}

// ---------------- launch ----------------
extern "C" void kernel_launch(void* const* d_in, const int* in_sizes, int n_in,
                              void* d_out, int out_size) {
    const float* x     = (const float*)d_in[0];
    const int*   ei    = (const int*)  d_in[1];
    const int*   batch = (const int*)  d_in[2];
    const float* ea    = (const float*)d_in[3];
    const float* W0 = (const float*)d_in[4];
    const float* b0 = (const float*)d_in[5];
    const float* g0 = (const float*)d_in[6];
    const float* be0 = (const float*)d_in[7];
    const float* W1 = (const float*)d_in[8];
    const float* b1 = (const float*)d_in[9];
    const float* g1 = (const float*)d_in[10];
    const float* be1 = (const float*)d_in[11];
    const float* W2 = (const float*)d_in[12];
    const float* b2 = (const float*)d_in[13];
    const float* W3 = (const float*)d_in[14];
    const float* b3 = (const float*)d_in[15];
    const float* Wfc = (const float*)d_in[16];
    const float* bfc = (const float*)d_in[17];
    float* out = (float*)d_out;

    const int* src = ei;
    const int* dst = ei + N_EDGES;

    const int TB = 256;
    int nB_nodes = (N_NODES + TB - 1) / TB;
    int nB_edges = (N_EDGES + TB - 1) / TB;
    int nScan1 = (N_NODES + 1023) / 1024;
    int nB_agg = (N_NODES * 32 + TB - 1) / TB;
    int nB_gemm = (N_NODES + 63) / 64;

    // dynamic smem sizes: Ws[C*64] + Xs[C*(64+2)]
    int smem128 = (128 * 64 + 128 * 66) * 4;   // 66560 B
    int smem64  = (64 * 64 + 64 * 66) * 4;     // 33280 B
    cudaFuncSetAttribute(gemm_kernel<128, false, false>,
                         cudaFuncAttributeMaxDynamicSharedMemorySize, smem128);
    cudaFuncSetAttribute(gemm_kernel<64, true, true>,
                         cudaFuncAttributeMaxDynamicSharedMemorySize, smem64);
    cudaFuncSetAttribute(gemm_kernel<64, true, false>,
                         cudaFuncAttributeMaxDynamicSharedMemorySize, smem64);

    // --- structure build ---
    zero_kernel<<<nB_nodes, TB>>>();
    degcnt_kernel<<<nB_edges, TB>>>(src, dst, ea);
    dinv_kernel<<<nB_nodes, TB>>>();
    scan1_kernel<<<nScan1, 1024>>>();
    scan2_kernel<<<1, 128>>>(nScan1);
    scan3_kernel<<<nB_nodes, TB>>>();
    csrfill_kernel<<<nB_edges, TB>>>(src, dst, ea);

    // --- layer 0: gemm(C=128, x) -> agg -> BN stats ---
    gemm_kernel<128, false, false><<<nB_gemm, 256, smem128>>>(x, W0, nullptr, nullptr, 0);
    agg_kernel<<<nB_agg, TB>>>(b0, 0);
    bnstats_kernel<<<512, 256>>>(0);
    bnfinal_kernel<<<1, 64>>>(0);

    // --- layer 1: gemm (BN0+lrelu fused on load) -> agg -> BN stats ---
    gemm_kernel<64, true, true><<<nB_gemm, 256, smem64>>>(nullptr, W1, g0, be0, 0);
    agg_kernel<<<nB_agg, TB>>>(b1, 0);
    bnstats_kernel<<<512, 256>>>(1);
    bnfinal_kernel<<<1, 64>>>(1);

    // --- layer 2: gemm (BN1+lrelu fused) -> agg(+lrelu) ---
    gemm_kernel<64, true, true><<<nB_gemm, 256, smem64>>>(nullptr, W2, g1, be1, 1);
    agg_kernel<<<nB_agg, TB>>>(b2, 1);

    // --- layer 3: gemm (raw g_h) -> agg(+lrelu) ---
    gemm_kernel<64, true, false><<<nB_gemm, 256, smem64>>>(nullptr, W3, nullptr, nullptr, 0);
    agg_kernel<<<nB_agg, TB>>>(b3, 1);

    // --- pooling + FC ---
    pool_kernel<<<N_GRAPHS, 256>>>(batch);
    fc_kernel<<<(N_GRAPHS * 32 + TB - 1) / TB, TB>>>(Wfc, bfc, out);
}

// round 4
// speedup vs baseline: 1.2196x; 1.0502x over previous
#include <cuda_runtime.h>
#include <math.h>

#define N_NODES 100000
#define N_EDGES 1600000
#define N_GRAPHS 256
#define C_IN 128
#define DD 64
#define EPS 1e-5f
#define SLOPE 0.01f

// ---------------- scratch (device globals; no cudaMalloc allowed) ----------
__device__ float  g_dinv[N_NODES];
__device__ float  g_dinv2[N_NODES];
__device__ float  g_deg[N_NODES];
__device__ int    g_cnt[N_NODES];
__device__ int    g_rowptr[N_NODES + 1];
__device__ int    g_fill[N_NODES];
__device__ int    g_bsum[128];
__device__ int    g_boff[128];
__device__ __align__(16) int2 g_epack[N_EDGES];   // {src, norm-as-int}, 16B aligned
__device__ float  g_t[N_NODES * DD];              // gemm output
__device__ float  g_h[N_NODES * DD];              // activations
__device__ double g_sum[2][DD];
__device__ double g_sumsq[2][DD];
__device__ float  g_mean[2][DD];
__device__ float  g_rstd[2][DD];
__device__ float  g_pooled[N_GRAPHS * 2 * DD];

// ---------------- f32x2 packed math helpers ----------------
__device__ __forceinline__ unsigned long long pk2(float lo, float hi) {
    unsigned long long r;
    asm("mov.b64 %0, {%1, %2};" : "=l"(r) : "f"(lo), "f"(hi));
    return r;
}
__device__ __forceinline__ void fma2(unsigned long long& d, unsigned long long a,
                                     unsigned long long b) {
    asm("fma.rn.f32x2 %0, %1, %2, %3;" : "=l"(d) : "l"(a), "l"(b), "l"(d));
}
__device__ __forceinline__ void upk2(float& lo, float& hi, unsigned long long v) {
    asm("mov.b64 {%0, %1}, %2;" : "=f"(lo), "=f"(hi) : "l"(v));
}

// ---------------- init / degree ----------------
__global__ void zero_kernel() {
    int i = blockIdx.x * blockDim.x + threadIdx.x;
    if (i < N_NODES) { g_deg[i] = 0.f; g_cnt[i] = 0; g_fill[i] = 0; }
    if (i < 128) {
        g_sum[i >> 6][i & 63] = 0.0;
        g_sumsq[i >> 6][i & 63] = 0.0;
    }
}

__global__ void degcnt_kernel(const int* __restrict__ src, const int* __restrict__ dst,
                              const float* __restrict__ w) {
    int e = blockIdx.x * blockDim.x + threadIdx.x;
    if (e < N_EDGES) {
        int d = dst[e];
        atomicAdd(&g_deg[d], w[e]);
        atomicAdd(&g_cnt[d], 1);
    }
}

__global__ void dinv_kernel() {
    int i = blockIdx.x * blockDim.x + threadIdx.x;
    if (i < N_NODES) {
        float dg = g_deg[i] + 1.0f;           // self loop weight 1
        float di = rsqrtf(dg);
        g_dinv[i]  = di;
        g_dinv2[i] = di * di;
    }
}

// ---------------- 3-phase exclusive scan of g_cnt -> g_rowptr ----------------
__global__ void scan1_kernel() {
    __shared__ int s[1024];
    int tid = threadIdx.x;
    int i = blockIdx.x * 1024 + tid;
    int v = (i < N_NODES) ? g_cnt[i] : 0;
    s[tid] = v;
    __syncthreads();
    for (int off = 1; off < 1024; off <<= 1) {
        int t = (tid >= off) ? s[tid - off] : 0;
        __syncthreads();
        s[tid] += t;
        __syncthreads();
    }
    if (i < N_NODES) g_rowptr[i] = s[tid] - v;
    if (tid == 1023) g_bsum[blockIdx.x] = s[1023];
}

__global__ void scan2_kernel(int nb) {
    __shared__ int s[128];
    int tid = threadIdx.x;
    int v = (tid < nb) ? g_bsum[tid] : 0;
    s[tid] = v;
    __syncthreads();
    for (int off = 1; off < 128; off <<= 1) {
        int t = (tid >= off) ? s[tid - off] : 0;
        __syncthreads();
        s[tid] += t;
        __syncthreads();
    }
    if (tid < nb) g_boff[tid] = s[tid] - v;
}

__global__ void scan3_kernel() {
    int i = blockIdx.x * blockDim.x + threadIdx.x;
    if (i < N_NODES) g_rowptr[i] += g_boff[i >> 10];
    if (i == 0) g_rowptr[N_NODES] = N_EDGES;
}

// ---------------- CSR fill (packed 8B records) ----------------
__global__ void csrfill_kernel(const int* __restrict__ src, const int* __restrict__ dst,
                               const float* __restrict__ w) {
    int e = blockIdx.x * blockDim.x + threadIdx.x;
    if (e < N_EDGES) {
        int d = dst[e], s = src[e];
        int pos = g_rowptr[d] + atomicAdd(&g_fill[d], 1);
        int2 pr;
        pr.x = s;
        pr.y = __float_as_int(g_dinv[s] * w[e] * g_dinv[d]);
        g_epack[pos] = pr;
    }
}

// ---------------- GEMM: X[N,C] @ W[C,64] -> g_t[N,64] with f32x2 FMAs ------
template<int C, bool FROM_GH, bool BNFUSE>
__global__ __launch_bounds__(256)
void gemm_kernel(const float* __restrict__ Xparam, const float* __restrict__ W,
                 const float* __restrict__ gamma, const float* __restrict__ beta,
                 int bnlayer) {
    constexpr int RPB = 64;
    constexpr int RPBp = RPB + 2;   // 8B-aligned padded column stride
    constexpr int RPT = 4;
    extern __shared__ float smem[];
    float* Ws = smem;               // [C][64]
    float* Xs = smem + C * 64;      // [C][RPBp], column-major tile

    const float* __restrict__ X = FROM_GH ? (const float*)g_h : Xparam;
    int tid = threadIdx.x;
    int rowBase = blockIdx.x * RPB;

    for (int idx = tid; idx < C * 64; idx += 256) Ws[idx] = W[idx];
    for (int idx = tid; idx < RPB * C; idx += 256) {
        int r = idx / C, c = idx % C;
        int gr = rowBase + r;
        float v = (gr < N_NODES) ? X[(size_t)gr * C + c] : 0.f;
        if (BNFUSE) {
            v = (v - g_mean[bnlayer][c]) * g_rstd[bnlayer][c] * gamma[c] + beta[c];
            v = v > 0.f ? v : SLOPE * v;
        }
        Xs[c * RPBp + r] = v;
    }
    __syncthreads();

    int tx = tid & 15, ty = tid >> 4;
    int rbase = ty * RPT;

    unsigned long long acc[RPT / 2][4];
#pragma unroll
    for (int p = 0; p < RPT / 2; p++)
#pragma unroll
        for (int j = 0; j < 4; j++) acc[p][j] = 0ull;

#pragma unroll 8
    for (int k = 0; k < C; k++) {
        float4 b = *(const float4*)(Ws + k * 64 + tx * 4);
        unsigned long long b0 = pk2(b.x, b.x);
        unsigned long long b1 = pk2(b.y, b.y);
        unsigned long long b2 = pk2(b.z, b.z);
        unsigned long long b3 = pk2(b.w, b.w);
        const float* col = Xs + k * RPBp + rbase;
#pragma unroll
        for (int p = 0; p < RPT / 2; p++) {
            unsigned long long a = *(const unsigned long long*)(col + p * 2);
            fma2(acc[p][0], a, b0);
            fma2(acc[p][1], a, b1);
            fma2(acc[p][2], a, b2);
            fma2(acc[p][3], a, b3);
        }
    }

#pragma unroll
    for (int p = 0; p < RPT / 2; p++) {
        float lo0, hi0, lo1, hi1, lo2, hi2, lo3, hi3;
        upk2(lo0, hi0, acc[p][0]);
        upk2(lo1, hi1, acc[p][1]);
        upk2(lo2, hi2, acc[p][2]);
        upk2(lo3, hi3, acc[p][3]);
        int gr0 = rowBase + rbase + p * 2;
        if (gr0 < N_NODES) {
            float4 v; v.x = lo0; v.y = lo1; v.z = lo2; v.w = lo3;
            *(float4*)(&g_t[gr0 * 64 + tx * 4]) = v;
        }
        if (gr0 + 1 < N_NODES) {
            float4 v; v.x = hi0; v.y = hi1; v.z = hi2; v.w = hi3;
            *(float4*)(&g_t[(gr0 + 1) * 64 + tx * 4]) = v;
        }
    }
}

// ---------------- aggregation: g_h = A @ g_t + bias (warp per node) --------
// 8-edge pipeline with 16B edge-record loads and L2-only gathers.
__device__ __forceinline__ float2 ldcg2(const float* p) {
    float2 v;
    asm volatile("ld.global.cg.v2.f32 {%0, %1}, [%2];"
                 : "=f"(v.x), "=f"(v.y) : "l"(p));
    return v;
}

__global__ void agg_kernel(const float* __restrict__ bias, int do_lrelu) {
    int w = (blockIdx.x * blockDim.x + threadIdx.x) >> 5;
    int lane2 = (threadIdx.x & 31) * 2;
    if (w >= N_NODES) return;

    float d2 = g_dinv2[w];
    float2 t0 = ldcg2(g_t + w * 64 + lane2);
    float ax = t0.x * d2, ay = t0.y * d2;

    int e = g_rowptr[w], end = g_rowptr[w + 1];

    // scalar prologue to reach 16B alignment of g_epack + e
    if ((e & 1) && e < end) {
        int2 p = g_epack[e];
        float2 v = ldcg2(g_t + p.x * 64 + lane2);
        float nn = __int_as_float(p.y);
        ax = fmaf(v.x, nn, ax); ay = fmaf(v.y, nn, ay);
        e++;
    }
    for (; e + 8 <= end; e += 8) {
        int4 pa = *(const int4*)(g_epack + e);       // edges e,   e+1
        int4 pb = *(const int4*)(g_epack + e + 2);   // edges e+2, e+3
        int4 pc = *(const int4*)(g_epack + e + 4);
        int4 pd = *(const int4*)(g_epack + e + 6);
        float2 v0 = ldcg2(g_t + pa.x * 64 + lane2);
        float2 v1 = ldcg2(g_t + pa.z * 64 + lane2);
        float2 v2 = ldcg2(g_t + pb.x * 64 + lane2);
        float2 v3 = ldcg2(g_t + pb.z * 64 + lane2);
        float2 v4 = ldcg2(g_t + pc.x * 64 + lane2);
        float2 v5 = ldcg2(g_t + pc.z * 64 + lane2);
        float2 v6 = ldcg2(g_t + pd.x * 64 + lane2);
        float2 v7 = ldcg2(g_t + pd.z * 64 + lane2);
        float n0 = __int_as_float(pa.y), n1 = __int_as_float(pa.w);
        float n2 = __int_as_float(pb.y), n3 = __int_as_float(pb.w);
        float n4 = __int_as_float(pc.y), n5 = __int_as_float(pc.w);
        float n6 = __int_as_float(pd.y), n7 = __int_as_float(pd.w);
        ax = fmaf(v0.x, n0, ax); ay = fmaf(v0.y, n0, ay);
        ax = fmaf(v1.x, n1, ax); ay = fmaf(v1.y, n1, ay);
        ax = fmaf(v2.x, n2, ax); ay = fmaf(v2.y, n2, ay);
        ax = fmaf(v3.x, n3, ax); ay = fmaf(v3.y, n3, ay);
        ax = fmaf(v4.x, n4, ax); ay = fmaf(v4.y, n4, ay);
        ax = fmaf(v5.x, n5, ax); ay = fmaf(v5.y, n5, ay);
        ax = fmaf(v6.x, n6, ax); ay = fmaf(v6.y, n6, ay);
        ax = fmaf(v7.x, n7, ax); ay = fmaf(v7.y, n7, ay);
    }
    for (; e < end; e++) {
        int2 p = g_epack[e];
        float2 v = ldcg2(g_t + p.x * 64 + lane2);
        float nn = __int_as_float(p.y);
        ax = fmaf(v.x, nn, ax); ay = fmaf(v.y, nn, ay);
    }
    ax += bias[lane2];
    ay += bias[lane2 + 1];
    if (do_lrelu) {
        ax = ax > 0.f ? ax : SLOPE * ax;
        ay = ay > 0.f ? ay : SLOPE * ay;
    }
    float2 o; o.x = ax; o.y = ay;
    *(float2*)(g_h + w * 64 + lane2) = o;
}

// ---------------- batch norm stats (block pre-reduced) ----------------
__global__ void bnstats_kernel(int layer) {
    __shared__ double ssum[256], ssq[256];
    int c = threadIdx.x & 63;
    int rlane = threadIdx.x >> 6;
    int r0 = blockIdx.x * 4 + rlane;
    int stride = gridDim.x * 4;
    double s = 0.0, s2 = 0.0;
    for (int r = r0; r < N_NODES; r += stride) {
        float v = g_h[r * 64 + c];
        s += (double)v;
        s2 += (double)v * (double)v;
    }
    ssum[threadIdx.x] = s;
    ssq[threadIdx.x]  = s2;
    __syncthreads();
    if (rlane == 0) {
#pragma unroll
        for (int j = 1; j < 4; j++) {
            s  += ssum[j * 64 + c];
            s2 += ssq[j * 64 + c];
        }
        atomicAdd(&g_sum[layer][c], s);
        atomicAdd(&g_sumsq[layer][c], s2);
    }
}

__global__ void bnfinal_kernel(int layer) {
    int c = threadIdx.x;
    if (c < DD) {
        double m = g_sum[layer][c] / (double)N_NODES;
        double var = g_sumsq[layer][c] / (double)N_NODES - m * m;
        g_mean[layer][c] = (float)m;
        g_rstd[layer][c] = rsqrtf((float)var + EPS);
    }
}

// ---------------- pooling (block per graph, batch is sorted) ----------------
__device__ __forceinline__ int lower_bound_dev(const int* a, int n, int key) {
    int lo = 0, hi = n;
    while (lo < hi) {
        int mid = (lo + hi) >> 1;
        if (a[mid] < key) lo = mid + 1; else hi = mid;
    }
    return lo;
}

__global__ void pool_kernel(const int* __restrict__ batch) {
    __shared__ int s_beg, s_end;
    __shared__ float smx[256], ssm[256];
    int g = blockIdx.x;
    if (threadIdx.x == 0) s_beg = lower_bound_dev(batch, N_NODES, g);
    if (threadIdx.x == 1) s_end = lower_bound_dev(batch, N_NODES, g + 1);
    __syncthreads();
    int beg = s_beg, end = s_end;

    int c = threadIdx.x & 63, grp = threadIdx.x >> 6;
    float mx = -3.402823466e38f;
    float sm = 0.f;
    for (int i = beg + grp; i < end; i += 4) {
        float v = g_h[i * 64 + c];
        mx = fmaxf(mx, v);
        sm += v;
    }
    smx[threadIdx.x] = mx;
    ssm[threadIdx.x] = sm;
    __syncthreads();
    if (grp == 0) {
        for (int j = 1; j < 4; j++) {
            mx = fmaxf(mx, smx[j * 64 + c]);
            sm += ssm[j * 64 + c];
        }
        int cnt = end - beg;
        float denom = (float)(cnt > 1 ? cnt : 1);
        g_pooled[g * 128 + c]      = mx;
        g_pooled[g * 128 + 64 + c] = sm / denom;
    }
}

// ---------------- FC: pooled[G,128] @ Wfc[128,1] + bfc ----------------
__global__ void fc_kernel(const float* __restrict__ Wfc, const float* __restrict__ bfc,
                          float* __restrict__ out) {
    int g = (blockIdx.x * blockDim.x + threadIdx.x) >> 5;
    int lane = threadIdx.x & 31;
    if (g >= N_GRAPHS) return;
    float s = 0.f;
    for (int i = lane; i < 128; i += 32) s += g_pooled[g * 128 + i] * Wfc[i];
#pragma unroll
    for (int o = 16; o; o >>= 1) s += __shfl_down_sync(0xFFFFFFFFu, s, o);
    if (lane == 0) out[g] = s + bfc[0];
}

// ---------------- side-stream resources (created once, uncaptured) ---------
struct Aux {
    cudaStream_t s1;
    cudaEvent_t eFork, eJoin;
    Aux() {
        cudaStreamCreateWithFlags(&s1, cudaStreamNonBlocking);
        cudaEventCreateWithFlags(&eFork, cudaEventDisableTiming);
        cudaEventCreateWithFlags(&eJoin, cudaEventDisableTiming);
    }
};
static Aux& aux() { static Aux a; return a; }

// ---------------- launch ----------------
extern "C" void kernel_launch(void* const* d_in, const int* in_sizes, int n_in,
                              void* d_out, int out_size) {
    const float* x     = (const float*)d_in[0];
    const int*   ei    = (const int*)  d_in[1];
    const int*   batch = (const int*)  d_in[2];
    const float* ea    = (const float*)d_in[3];
    const float* W0 = (const float*)d_in[4];
    const float* b0 = (const float*)d_in[5];
    const float* g0 = (const float*)d_in[6];
    const float* be0 = (const float*)d_in[7];
    const float* W1 = (const float*)d_in[8];
    const float* b1 = (const float*)d_in[9];
    const float* g1 = (const float*)d_in[10];
    const float* be1 = (const float*)d_in[11];
    const float* W2 = (const float*)d_in[12];
    const float* b2 = (const float*)d_in[13];
    const float* W3 = (const float*)d_in[14];
    const float* b3 = (const float*)d_in[15];
    const float* Wfc = (const float*)d_in[16];
    const float* bfc = (const float*)d_in[17];
    float* out = (float*)d_out;

    const int* src = ei;
    const int* dst = ei + N_EDGES;

    const int TB = 256;
    int nB_nodes = (N_NODES + TB - 1) / TB;
    int nB_edges = (N_EDGES + TB - 1) / TB;
    int nScan1 = (N_NODES + 1023) / 1024;
    int nB_agg = (N_NODES * 32 + TB - 1) / TB;
    int nB_gemm = (N_NODES + 63) / 64;

    int smem128 = (128 * 64 + 128 * 66) * 4;   // 66560 B
    int smem64  = (64 * 64 + 64 * 66) * 4;     // 33280 B
    cudaFuncSetAttribute(gemm_kernel<128, false, false>,
                         cudaFuncAttributeMaxDynamicSharedMemorySize, smem128);
    cudaFuncSetAttribute(gemm_kernel<64, true, true>,
                         cudaFuncAttributeMaxDynamicSharedMemorySize, smem64);
    cudaFuncSetAttribute(gemm_kernel<64, true, false>,
                         cudaFuncAttributeMaxDynamicSharedMemorySize, smem64);

    Aux& A = aux();

    // --- fork: structure build on side stream, gemm0 on main stream -------
    cudaEventRecord(A.eFork, 0);
    cudaStreamWaitEvent(A.s1, A.eFork, 0);

    zero_kernel<<<nB_nodes, TB, 0, A.s1>>>();
    degcnt_kernel<<<nB_edges, TB, 0, A.s1>>>(src, dst, ea);
    dinv_kernel<<<nB_nodes, TB, 0, A.s1>>>();
    scan1_kernel<<<nScan1, 1024, 0, A.s1>>>();
    scan2_kernel<<<1, 128, 0, A.s1>>>(nScan1);
    scan3_kernel<<<nB_nodes, TB, 0, A.s1>>>();
    csrfill_kernel<<<nB_edges, TB, 0, A.s1>>>(src, dst, ea);
    cudaEventRecord(A.eJoin, A.s1);

    // main stream: layer-0 GEMM runs concurrently with the build
    gemm_kernel<128, false, false><<<nB_gemm, 256, smem128>>>(x, W0, nullptr, nullptr, 0);

    // join: aggregation needs both CSR and gemm0
    cudaStreamWaitEvent(0, A.eJoin, 0);

    // --- layer 0 ---
    agg_kernel<<<nB_agg, TB>>>(b0, 0);
    bnstats_kernel<<<512, 256>>>(0);
    bnfinal_kernel<<<1, 64>>>(0);

    // --- layer 1 ---
    gemm_kernel<64, true, true><<<nB_gemm, 256, smem64>>>(nullptr, W1, g0, be0, 0);
    agg_kernel<<<nB_agg, TB>>>(b1, 0);
    bnstats_kernel<<<512, 256>>>(1);
    bnfinal_kernel<<<1, 64>>>(1);

    // --- layer 2 ---
    gemm_kernel<64, true, true><<<nB_gemm, 256, smem64>>>(nullptr, W2, g1, be1, 1);
    agg_kernel<<<nB_agg, TB>>>(b2, 1);

    // --- layer 3 ---
    gemm_kernel<64, true, false><<<nB_gemm, 256, smem64>>>(nullptr, W3, nullptr, nullptr, 0);
    agg_kernel<<<nB_agg, TB>>>(b3, 1);

    // --- pooling + FC ---
    pool_kernel<<<N_GRAPHS, 256>>>(batch);
    fc_kernel<<<(N_GRAPHS * 32 + TB - 1) / TB, TB>>>(Wfc, bfc, out);
}